// round 15
// baseline (speedup 1.0000x reference)
#include <cuda_runtime.h>
#include <cuda_fp16.h>
#include <cstdint>

#define NB 8
#define NC 256
#define HW 4096
#define DH 128
#define NO 256

#define QTILE 128
#define KTILE 128
#define STRD 136         // smem row stride in halves (272B, conflict-free)

#define NITEMS 2048      // 8 b x 32 qtiles x 8 key-chunks (512 keys each)

// Scratch: projected q (pre-scaled by 128^-0.5 * log2(e)) and k, [b][token][d]
// fp16. exp(S) == exp2(S') with folded scale.
__device__ __half g_Q[(size_t)NB * HW * DH];
__device__ __half g_K[(size_t)NB * HW * DH];
// Partial exp-sums: [b][qtile][kchunk][row] (1 MB)
__device__ float g_Lpart[(size_t)NB * 32 * 8 * 128];
// Monotonic grid-barrier counter (zero-initialized; replay-safe epochs).
__device__ unsigned int g_bar;

__device__ __forceinline__ void mma_f16(float c[4], const uint32_t a[4],
                                        const uint32_t b[2]) {
    asm volatile(
        "mma.sync.aligned.m16n8k16.row.col.f32.f16.f16.f32 "
        "{%0,%1,%2,%3}, {%4,%5,%6,%7}, {%8,%9}, {%0,%1,%2,%3};"
        : "+f"(c[0]), "+f"(c[1]), "+f"(c[2]), "+f"(c[3])
        : "r"(a[0]), "r"(a[1]), "r"(a[2]), "r"(a[3]), "r"(b[0]), "r"(b[1]));
}

__device__ __forceinline__ void ldsm_x4(uint32_t r[4], uint32_t saddr) {
    asm volatile("ldmatrix.sync.aligned.m8n8.x4.shared.b16 {%0,%1,%2,%3}, [%4];"
                 : "=r"(r[0]), "=r"(r[1]), "=r"(r[2]), "=r"(r[3]) : "r"(saddr));
}

__device__ __forceinline__ void ldsm_x4_t(uint32_t r[4], uint32_t saddr) {
    asm volatile("ldmatrix.sync.aligned.m8n8.x4.trans.shared.b16 {%0,%1,%2,%3}, [%4];"
                 : "=r"(r[0]), "=r"(r[1]), "=r"(r[2]), "=r"(r[3]) : "r"(saddr));
}

__device__ __forceinline__ float ex2f(float x) {
    float y;
    asm("ex2.approx.f32 %0, %1;" : "=f"(y) : "f"(x));
    return y;
}

__device__ __forceinline__ void cp_async16(uint32_t saddr, const void* gptr) {
    asm volatile("cp.async.cg.shared.global [%0], [%1], 16;"
                 :: "r"(saddr), "l"(gptr) : "memory");
}
#define CP_COMMIT() asm volatile("cp.async.commit_group;" ::: "memory")
#define CP_WAIT(n)  asm volatile("cp.async.wait_group %0;" :: "n"(n) : "memory")

__device__ __forceinline__ void stcs_f2(float* p, float2 v) {
    asm volatile("st.global.cs.v2.f32 [%0], {%1, %2};" :: "l"(p), "f"(v.x), "f"(v.y)
                 : "memory");
}

// item id -> (batch, qtile, key-chunk)
__device__ __forceinline__ void item_decode(int g, int& b, int& qt, int& kc) {
    b = g >> 8; int r = g & 255; qt = r >> 3; kc = r & 7;
}

__device__ __forceinline__ void prefetch_ktile(uint32_t KsAddr, int nbuf,
                                               const __half* src, int tid) {
    const uint32_t dsta = KsAddr + (uint32_t)(nbuf * KTILE * STRD) * 2;
    #pragma unroll
    for (int i = 0; i < 8; i++) {
        int f = tid + i * 256;
        int row = f >> 4;
        int c16 = f & 15;
        cp_async16(dsta + (uint32_t)(row * STRD + c16 * 8) * 2,
                   src + (size_t)row * DH + c16 * 8);
    }
    CP_COMMIT();
}

// ---------------------------------------------------------------------------
// Kernel 1: projection on fp16 tensor cores (unchanged from R14).
// ---------------------------------------------------------------------------
#define PKT 64
#define XS 136
#define WS 72

__global__ __launch_bounds__(256, 2) void proj2_kernel(const float* __restrict__ x,
                                                       const float* __restrict__ W) {
    __shared__ __half Xs[PKT][XS];
    __shared__ __half Ws[128][WS];
    const int n0 = blockIdx.x * 128;
    const int oh = blockIdx.y;
    const int b  = blockIdx.z;
    const int tid = threadIdx.x;
    const int wid = tid >> 5;
    const int lane = tid & 31;
    const int gid = lane >> 2;
    const int tid4 = lane & 3;
    const int mw = wid >> 2;
    const int nw = wid & 3;
    const int wm0 = mw * 64;
    const int wn0 = nw * 32;

    const float* xb = x + (size_t)b * NC * HW + n0;
    const float* Wb = W + (size_t)oh * 128 * NC;

    const uint32_t XsA = (uint32_t)__cvta_generic_to_shared(Xs);
    const uint32_t WsA = (uint32_t)__cvta_generic_to_shared(Ws);

    const int aKrow = (lane & 7) + ((lane & 16) ? 8 : 0);
    const int aMcol = (lane & 8) ? 8 : 0;
    const int bRow = (lane & 7) + ((lane & 16) ? 8 : 0);
    const int bCol = (lane & 8) ? 8 : 0;

    float acc[4][4][4] = {};

    for (int kt = 0; kt < NC / PKT; kt++) {
        __syncthreads();
        #pragma unroll
        for (int i = 0; i < 8; i++) {
            int f = tid + i * 256;
            int row = f >> 5;
            int c4  = f & 31;
            float4 v = *(const float4*)(xb + (size_t)(kt * PKT + row) * HW + c4 * 4);
            __half2 h0 = __floats2half2_rn(v.x, v.y);
            __half2 h1 = __floats2half2_rn(v.z, v.w);
            uint2 u; u.x = *(uint32_t*)&h0; u.y = *(uint32_t*)&h1;
            *(uint2*)&Xs[row][c4 * 4] = u;
        }
        #pragma unroll
        for (int i = 0; i < 8; i++) {
            int f = tid + i * 256;
            int row = f >> 4;
            int c4  = f & 15;
            float4 v = *(const float4*)(Wb + (size_t)row * NC + kt * PKT + c4 * 4);
            __half2 h0 = __floats2half2_rn(v.x, v.y);
            __half2 h1 = __floats2half2_rn(v.z, v.w);
            uint2 u; u.x = *(uint32_t*)&h0; u.y = *(uint32_t*)&h1;
            *(uint2*)&Ws[row][c4 * 4] = u;
        }
        __syncthreads();

        #pragma unroll
        for (int ks = 0; ks < PKT / 16; ks++) {
            const int ko = ks * 16;
            uint32_t a[4][4], bf[2][4];
            #pragma unroll
            for (int mf = 0; mf < 4; mf++)
                ldsm_x4_t(a[mf], XsA + (uint32_t)((ko + aKrow) * XS
                                                  + wm0 + mf * 16 + aMcol) * 2);
            #pragma unroll
            for (int np = 0; np < 2; np++)
                ldsm_x4(bf[np], WsA + (uint32_t)((wn0 + np * 16 + bRow) * WS
                                                 + ko + bCol) * 2);
            #pragma unroll
            for (int mf = 0; mf < 4; mf++) {
                mma_f16(acc[mf][0], a[mf], &bf[0][0]);
                mma_f16(acc[mf][1], a[mf], &bf[0][2]);
                mma_f16(acc[mf][2], a[mf], &bf[1][0]);
                mma_f16(acc[mf][3], a[mf], &bf[1][2]);
            }
        }
    }

    const float s = (oh == 0) ? 0.088388347648318447f * 1.4426950408889634f : 1.0f;
    __half* dst = ((oh == 0) ? g_Q : g_K) + (size_t)b * HW * DH;
    #pragma unroll
    for (int mf = 0; mf < 4; mf++)
        #pragma unroll
        for (int h = 0; h < 2; h++) {
            const int n = n0 + wm0 + mf * 16 + h * 8 + gid;
            #pragma unroll
            for (int nf = 0; nf < 4; nf++) {
                const int o = wn0 + nf * 8 + tid4 * 2;
                __half2 hv = __floats2half2_rn(acc[mf][nf][h * 2 + 0] * s,
                                               acc[mf][nf][h * 2 + 1] * s);
                *(__half2*)(dst + (size_t)n * DH + o) = hv;
            }
        }
}

// ---------------------------------------------------------------------------
// Kernel 2: fused persistent attention (pass0 expsum + grid barrier + pass1
// normalize-and-store). Grid = 2 x SM count (all CTAs co-resident: regs<=128,
// smem 106.5 KB -> exactly 2 CTA/SM). Work item = (b, qtile, 512-key chunk).
// CTA c handles items c, c+G, c+2G, ... in both passes.
// ---------------------------------------------------------------------------
extern __shared__ char smx[];
#define QS_BYTES (QTILE * STRD * 2)
#define KS_BYTES (KTILE * STRD * 2)
#define SMEM_ATTN (QS_BYTES + 2 * KS_BYTES + 128 * 4 * sizeof(float))

__global__ __launch_bounds__(256, 2) void attn_fused_kernel(float* __restrict__ out) {
    __half* Qs = (__half*)smx;
    __half* Ks = (__half*)(smx + QS_BYTES);
    float* LRed = (float*)(smx + QS_BYTES + 2 * KS_BYTES);

    const int G = gridDim.x;
    const int c = blockIdx.x;
    const int baseIt = NITEMS / G;
    const int nIt = baseIt + ((c < NITEMS - baseIt * G) ? 1 : 0);
    const int nSteps = nIt * 4;

    const int tid = threadIdx.x;
    const int wid = tid >> 5;
    const int lane = tid & 31;
    const int gid = lane >> 2;
    const int tid4 = lane & 3;
    const int mw = wid >> 2;
    const int nw = wid & 3;
    const int wm0 = mw * 64;
    const int wn0 = nw * 32;

    const uint32_t QsAddr = (uint32_t)__cvta_generic_to_shared(Qs);
    const uint32_t KsAddr = (uint32_t)__cvta_generic_to_shared(Ks);

    const int aRow = wm0 + (lane & 15);
    const int aCol = (lane & 16) ? 8 : 0;
    const uint32_t aBase = QsAddr + (uint32_t)(aRow * STRD + aCol) * 2;
    const int bRow = wn0 + (lane & 7) + ((lane & 16) ? 8 : 0);
    const int bCol = (lane & 8) ? 8 : 0;
    const uint32_t bBase = KsAddr + (uint32_t)(bRow * STRD + bCol) * 2;

    // ======================== PASS 0: expsum ========================
    if (nSteps > 0) {
        int b0, qt0, kc0;
        item_decode(c, b0, qt0, kc0);
        prefetch_ktile(KsAddr, 0, g_K + ((size_t)b0 * HW + kc0 * 512) * DH, tid);
    }

    int curB = 0, curQt = 0, curKc = 0;
    float Lp[4][2];

    for (int step = 0; step < nSteps; step++) {
        const int buf = step & 1;

        CP_WAIT(0);
        __syncthreads();

        const bool newItem = (step & 3) == 0;
        if (newItem) {
            item_decode((step >> 2) * G + c, curB, curQt, curKc);
            const __half* Qg = g_Q + ((size_t)curB * HW + curQt * 128) * DH;
            #pragma unroll
            for (int i = 0; i < 8; i++) {
                int f = tid + i * 256;
                int row = f >> 4;
                int c16 = f & 15;
                *(float4*)(Qs + row * STRD + c16 * 8) =
                    *(const float4*)(Qg + (size_t)row * DH + c16 * 8);
            }
            #pragma unroll
            for (int mf = 0; mf < 4; mf++) { Lp[mf][0] = 0.0f; Lp[mf][1] = 0.0f; }
        }

        if (step + 1 < nSteps) {
            const int ns = step + 1;
            int nb, nqt, nkc;
            item_decode((ns >> 2) * G + c, nb, nqt, nkc);
            prefetch_ktile(KsAddr, ns & 1,
                           g_K + ((size_t)nb * HW + nkc * 512 + (ns & 3) * 128) * DH,
                           tid);
        }
        if (newItem) __syncthreads();

        const uint32_t bTile = bBase + (uint32_t)(buf * KTILE * STRD) * 2;

        float acc[4][4][4] = {};
        #pragma unroll
        for (int ks = 0; ks < 8; ks++) {
            const int ko = ks * 16;
            uint32_t a[4][4], bf[2][4];
            #pragma unroll
            for (int mf = 0; mf < 4; mf++)
                ldsm_x4(a[mf], aBase + (uint32_t)(mf * 16 * STRD + ko) * 2);
            #pragma unroll
            for (int np = 0; np < 2; np++)
                ldsm_x4(bf[np], bTile + (uint32_t)(np * 16 * STRD + ko) * 2);
            #pragma unroll
            for (int mf = 0; mf < 4; mf++) {
                mma_f16(acc[mf][0], a[mf], &bf[0][0]);
                mma_f16(acc[mf][1], a[mf], &bf[0][2]);
                mma_f16(acc[mf][2], a[mf], &bf[1][0]);
                mma_f16(acc[mf][3], a[mf], &bf[1][2]);
            }
        }

        // exp-sum in f16x2 (halves MUFU); errors average out in L.
        #pragma unroll
        for (int mf = 0; mf < 4; mf++) {
            __half2 s0 = __float2half2_rn(0.0f), s1 = __float2half2_rn(0.0f);
            #pragma unroll
            for (int nf = 0; nf < 4; nf++) {
                s0 = __hadd2(s0, h2exp2(__floats2half2_rn(acc[mf][nf][0],
                                                          acc[mf][nf][1])));
                s1 = __hadd2(s1, h2exp2(__floats2half2_rn(acc[mf][nf][2],
                                                          acc[mf][nf][3])));
            }
            Lp[mf][0] += __low2float(s0) + __high2float(s0);
            Lp[mf][1] += __low2float(s1) + __high2float(s1);
        }

        if ((step & 3) == 3) {
            #pragma unroll
            for (int mf = 0; mf < 4; mf++)
                #pragma unroll
                for (int h = 0; h < 2; h++) {
                    float v = Lp[mf][h];
                    v += __shfl_xor_sync(0xffffffffu, v, 1);
                    v += __shfl_xor_sync(0xffffffffu, v, 2);
                    if (tid4 == 0)
                        LRed[(wm0 + mf * 16 + h * 8 + gid) * 4 + nw] = v;
                }
            __syncthreads();
            if (nw == 0 && tid4 == 0) {
                float* dst = g_Lpart + (((size_t)curB * 32 + curQt) * 8 + curKc) * 128;
                #pragma unroll
                for (int mf = 0; mf < 4; mf++)
                    #pragma unroll
                    for (int h = 0; h < 2; h++) {
                        const int row = wm0 + mf * 16 + h * 8 + gid;
                        const float* lr = LRed + row * 4;
                        dst[row] = lr[0] + lr[1] + lr[2] + lr[3];
                    }
            }
        }
    }

    // Prefetch pass-1's first K tile (independent of pass-0 results) so the
    // load runs during the barrier wait.
    if (nSteps > 0) {
        int b0, qt0, kc0;
        item_decode(c, b0, qt0, kc0);
        prefetch_ktile(KsAddr, 0, g_K + ((size_t)b0 * HW + kc0 * 512) * DH, tid);
    }

    // ================== grid-wide barrier (epoch-based) ==================
    __threadfence();
    __syncthreads();
    if (tid == 0) {
        unsigned int ticket = atomicAdd(&g_bar, 1u);
        unsigned int target = (ticket / (unsigned)G + 1u) * (unsigned)G;
        unsigned int cur;
        do {
            asm volatile("ld.acquire.gpu.u32 %0, [%1];"
                         : "=r"(cur) : "l"(&g_bar) : "memory");
        } while (cur < target);
    }
    __syncthreads();

    // ======================== PASS 1: normalize ========================
    float iL[4][2];

    for (int step = 0; step < nSteps; step++) {
        const int buf = step & 1;

        CP_WAIT(0);
        __syncthreads();

        const bool newItem = (step & 3) == 0;
        if (newItem) {
            item_decode((step >> 2) * G + c, curB, curQt, curKc);
            const __half* Qg = g_Q + ((size_t)curB * HW + curQt * 128) * DH;
            #pragma unroll
            for (int i = 0; i < 8; i++) {
                int f = tid + i * 256;
                int row = f >> 4;
                int c16 = f & 15;
                *(float4*)(Qs + row * STRD + c16 * 8) =
                    *(const float4*)(Qg + (size_t)row * DH + c16 * 8);
            }
            if (tid < 128) {
                const float* lp = g_Lpart + ((size_t)curB * 32 + curQt) * 8 * 128 + tid;
                float s = 0.0f;
                #pragma unroll
                for (int j = 0; j < 8; j++) s += lp[j * 128];
                LRed[tid] = 1.0f / s;
            }
        }

        if (step + 1 < nSteps) {
            const int ns = step + 1;
            int nb, nqt, nkc;
            item_decode((ns >> 2) * G + c, nb, nqt, nkc);
            prefetch_ktile(KsAddr, ns & 1,
                           g_K + ((size_t)nb * HW + nkc * 512 + (ns & 3) * 128) * DH,
                           tid);
        }
        if (newItem) {
            __syncthreads();
            #pragma unroll
            for (int mf = 0; mf < 4; mf++)
                #pragma unroll
                for (int h = 0; h < 2; h++)
                    iL[mf][h] = LRed[wm0 + mf * 16 + h * 8 + gid];
        }

        const uint32_t bTile = bBase + (uint32_t)(buf * KTILE * STRD) * 2;

        float acc[4][4][4] = {};
        #pragma unroll
        for (int ks = 0; ks < 8; ks++) {
            const int ko = ks * 16;
            uint32_t a[4][4], bf[2][4];
            #pragma unroll
            for (int mf = 0; mf < 4; mf++)
                ldsm_x4(a[mf], aBase + (uint32_t)(mf * 16 * STRD + ko) * 2);
            #pragma unroll
            for (int np = 0; np < 2; np++)
                ldsm_x4(bf[np], bTile + (uint32_t)(np * 16 * STRD + ko) * 2);
            #pragma unroll
            for (int mf = 0; mf < 4; mf++) {
                mma_f16(acc[mf][0], a[mf], &bf[0][0]);
                mma_f16(acc[mf][1], a[mf], &bf[0][2]);
                mma_f16(acc[mf][2], a[mf], &bf[1][0]);
                mma_f16(acc[mf][3], a[mf], &bf[1][2]);
            }
        }

        const int col0 = curKc * 512 + (step & 3) * 128 + wn0 + tid4 * 2;
        #pragma unroll
        for (int mf = 0; mf < 4; mf++) {
            const int row = curQt * 128 + wm0 + mf * 16 + gid;
            float* o0p = out + ((size_t)curB * HW + row) * HW + col0;
            float* o1p = o0p + 8 * (size_t)HW;
            #pragma unroll
            for (int nf = 0; nf < 4; nf++) {
                float2 v0, v1;
                v0.x = ex2f(acc[mf][nf][0]) * iL[mf][0];
                v0.y = ex2f(acc[mf][nf][1]) * iL[mf][0];
                v1.x = ex2f(acc[mf][nf][2]) * iL[mf][1];
                v1.y = ex2f(acc[mf][nf][3]) * iL[mf][1];
                stcs_f2(o0p + nf * 8, v0);
                stcs_f2(o1p + nf * 8, v1);
            }
        }
    }
}

extern "C" void kernel_launch(void* const* d_in, const int* in_sizes, int n_in,
                              void* d_out, int out_size) {
    (void)in_sizes; (void)n_in; (void)out_size;
    const float* x = (const float*)d_in[0];   // (8, 256, 64, 64) fp32
    const float* W = (const float*)d_in[1];   // (256, 256) fp32
    float* out = (float*)d_out;               // (8, 1, 4096, 4096) fp32

    proj2_kernel<<<dim3(HW / 128, 2, NB), 256>>>(x, W);

    int nsm = 148;
    cudaDeviceGetAttribute(&nsm, cudaDevAttrMultiProcessorCount, 0);
    const int grid = 2 * nsm;   // all CTAs co-resident (2/SM) -> barrier is safe

    cudaFuncSetAttribute(attn_fused_kernel,
                         cudaFuncAttributeMaxDynamicSharedMemorySize, SMEM_ATTN);
    attn_fused_kernel<<<grid, 256, SMEM_ATTN>>>(out);
}